// round 9
// baseline (speedup 1.0000x reference)
#include <cuda_runtime.h>
#include <cuda_bf16.h>
#include <cstdint>

// CrossSetNorm: x[B=2048, S=328, D=256] f32, mask[B,S] int32 (nonzero = dead).
// R8: eighth-width tiles (200x32 f, 25KB), 256-thread CTAs, 8 CTAs/SM.
// Barrier-free load->sum path: each thread sums ONLY the float4s it itself
// cp.async'd (self-visibility after wait_group), with alive flags held in a
// per-thread bitmask register (LDG from gmem mask). Two commit groups let
// summation start while the tile tail streams.

#define B_TOT   2048
#define S_TOT   328
#define D_FEAT  256
#define D_8TH   32
#define S_OBJ   128
#define S_ROAD  200
#define NTHREADS 256

// Shared memory layout (float slots), per CTA:
//   [0, 6400)       raw x tile (200 rows x 8 float4)
//   [6400, 6528)    r1 fold scratch [4][32]
//   [6528, 6656)    r2 fold scratch [4][32]
//   [6656, 6688)    a[32]
//   [6688, 6720)    c[32]
//   [6720, 6920)    mask ints (200)  (for the count warp only)
//   [6920]          count
#define OFF_DATA   0
#define OFF_R1     6400
#define OFF_R2     6528
#define OFF_A      6656
#define OFF_C      6688
#define OFF_MASK   6720
#define OFF_CNT    6920
#define SMEM_FLOATS 6924
#define SMEM_BYTES (SMEM_FLOATS * 4)   // 27696 B; x8 CTAs ~= 222KB/SM

__device__ __forceinline__ void cp_async16(uint32_t smem_addr, const void* gptr) {
    asm volatile("cp.async.cg.shared.global [%0], [%1], 16;\n"
                 :: "r"(smem_addr), "l"(gptr) : "memory");
}

__global__ void __launch_bounds__(NTHREADS, 8)
cross_set_norm_kernel(const float* __restrict__ x,
                      const int* __restrict__ mask,
                      const float* __restrict__ w_obj,
                      const float* __restrict__ b_obj,
                      const float* __restrict__ w_road,
                      const float* __restrict__ b_road,
                      float* __restrict__ out)
{
    extern __shared__ float smem[];

    const int bid    = blockIdx.x;
    const int eighth = bid & 7;           // feature eighth
    const int seg    = (bid >> 3) & 1;    // 0 = obj, 1 = road
    const int b      = bid >> 4;

    const int S   = seg ? S_ROAD : S_OBJ;
    const int off = seg ? S_OBJ : 0;
    const int fo  = eighth * D_8TH;
    const float* __restrict__ wseg = (seg ? w_road : w_obj) + fo;
    const float* __restrict__ bseg = (seg ? b_road : b_obj) + fo;

    const size_t row_base = ((size_t)b * S_TOT + off);
    const float* xin  = x    + row_base * D_FEAT + fo;
    float*       outp = out  + row_base * D_FEAT + fo;
    const int*   m    = mask + row_base;

    const int tid  = threadIdx.x;
    const int tx   = tid & 7;    // float4 column: features [4*tx, 4*tx+4) in eighth
    const int ty   = tid >> 3;   // 0..31 row
    const int lane = tid & 31;
    const int wrp  = tid >> 5;   // 0..7
    const unsigned FULL = 0xffffffffu;

    // ---- Phase A: fire tile via cp.async in two commit groups ---------
    uint32_t sdata = (uint32_t)__cvta_generic_to_shared(smem + OFF_DATA);
    // group A: rows ty, ty+32, ty+64 (always < 96 <= S) + smem mask copy
    #pragma unroll
    for (int i = 0; i < 3; i++) {
        int s = ty + 32 * i;
        cp_async16(sdata + (uint32_t)(s * 8 + tx) * 16,
                   xin + (size_t)s * D_FEAT + tx * 4);
    }
    {
        uint32_t smask = (uint32_t)__cvta_generic_to_shared(smem + OFF_MASK);
        if (tid < (S >> 2)) cp_async16(smask + (uint32_t)tid * 16, m + tid * 4);
    }
    asm volatile("cp.async.commit_group;\n" ::: "memory");
    // group B: remaining rows
    #pragma unroll
    for (int i = 3; i < 7; i++) {
        int s = ty + 32 * i;
        if (s < S) {
            cp_async16(sdata + (uint32_t)(s * 8 + tx) * 16,
                       xin + (size_t)s * D_FEAT + tx * 4);
        }
    }
    asm volatile("cp.async.commit_group;\n" ::: "memory");

    // per-thread alive bitmask for own rows (independent LDGs, tiny)
    unsigned amask = 0;
    #pragma unroll
    for (int i = 0; i < 7; i++) {
        int s = ty + 32 * i;
        if (s < S && __ldg(m + s) == 0) amask |= (1u << i);
    }
    // prefetch per-feature weight/bias for the coeff phase
    float wv = 0.f, bv = 0.f;
    if (tid < D_8TH) { wv = __ldg(wseg + tid); bv = __ldg(bseg + tid); }

    float4* datav = reinterpret_cast<float4*>(smem + OFF_DATA);

    // ---- Phase B: barrier-free sum of self-owned data -----------------
    float s1x = 0.f, s1y = 0.f, s1z = 0.f, s1w = 0.f;
    float s2x = 0.f, s2y = 0.f, s2z = 0.f, s2w = 0.f;

    asm volatile("cp.async.wait_group 1;\n" ::: "memory");
    #pragma unroll
    for (int i = 0; i < 3; i++) {
        int s = ty + 32 * i;
        float al = (float)((amask >> i) & 1u);
        float4 v = datav[s * 8 + tx];
        v.x *= al; v.y *= al; v.z *= al; v.w *= al;
        s1x += v.x; s1y += v.y; s1z += v.z; s1w += v.w;
        s2x += v.x * v.x; s2y += v.y * v.y; s2z += v.z * v.z; s2w += v.w * v.w;
    }
    asm volatile("cp.async.wait_group 0;\n" ::: "memory");
    #pragma unroll
    for (int i = 3; i < 7; i++) {
        int s = ty + 32 * i;
        if (s < S) {
            float al = (float)((amask >> i) & 1u);
            float4 v = datav[s * 8 + tx];
            v.x *= al; v.y *= al; v.z *= al; v.w *= al;
            s1x += v.x; s1y += v.y; s1z += v.z; s1w += v.w;
            s2x += v.x * v.x; s2y += v.y * v.y; s2z += v.z * v.z; s2w += v.w * v.w;
        }
    }

    // intra-warp folds: lane layout tx=lane&7, tyw=lane>>3
    s1x += __shfl_down_sync(FULL, s1x, 16); s1y += __shfl_down_sync(FULL, s1y, 16);
    s1z += __shfl_down_sync(FULL, s1z, 16); s1w += __shfl_down_sync(FULL, s1w, 16);
    s2x += __shfl_down_sync(FULL, s2x, 16); s2y += __shfl_down_sync(FULL, s2y, 16);
    s2z += __shfl_down_sync(FULL, s2z, 16); s2w += __shfl_down_sync(FULL, s2w, 16);
    s1x += __shfl_down_sync(FULL, s1x, 8);  s1y += __shfl_down_sync(FULL, s1y, 8);
    s1z += __shfl_down_sync(FULL, s1z, 8);  s1w += __shfl_down_sync(FULL, s1w, 8);
    s2x += __shfl_down_sync(FULL, s2x, 8);  s2y += __shfl_down_sync(FULL, s2y, 8);
    s2z += __shfl_down_sync(FULL, s2z, 8);  s2w += __shfl_down_sync(FULL, s2w, 8);
    // lanes 0..7 now hold this warp's per-feature partials

    float4* r1 = reinterpret_cast<float4*>(smem + OFF_R1);
    float4* r2 = reinterpret_cast<float4*>(smem + OFF_R2);
    if (wrp >= 4 && lane < 8) {
        r1[(wrp - 4) * 8 + lane] = make_float4(s1x, s1y, s1z, s1w);
        r2[(wrp - 4) * 8 + lane] = make_float4(s2x, s2y, s2z, s2w);
    }
    __syncthreads();
    if (wrp < 4 && lane < 8) {
        float4 p1 = r1[wrp * 8 + lane];
        float4 p2 = r2[wrp * 8 + lane];
        p1.x += s1x; p1.y += s1y; p1.z += s1z; p1.w += s1w;
        p2.x += s2x; p2.y += s2y; p2.z += s2z; p2.w += s2w;
        r1[wrp * 8 + lane] = p1;
        r2[wrp * 8 + lane] = p2;
    }
    __syncthreads();

    // ---- Phase C: final reduce (32 threads) + count (warp 1) ----------
    const int* mint = reinterpret_cast<const int*>(smem + OFF_MASK);
    if (tid < D_8TH) {
        float S1 = 0.f, S2 = 0.f;
        #pragma unroll
        for (int k = 0; k < 4; k++) {
            S1 += smem[OFF_R1 + k * 32 + tid];
            S2 += smem[OFF_R2 + k * 32 + tid];
        }
        // stash: coeffs computed after count arrives (below, same threads)
        smem[OFF_R1 + tid] = S1;   // reuse scratch row 0
        smem[OFF_R2 + tid] = S2;
    } else if (tid < 64) {
        float c = 0.f;
        for (int s = lane; s < S; s += 32) c += (mint[s] ? 0.0f : 1.0f);
        #pragma unroll
        for (int o = 16; o > 0; o >>= 1) c += __shfl_down_sync(FULL, c, o);
        if (lane == 0) smem[OFF_CNT] = c;
    }
    __syncthreads();

    if (tid < D_8TH) {
        float S1 = smem[OFF_R1 + tid];
        float S2 = smem[OFF_R2 + tid];
        float cnt = smem[OFF_CNT];
        float cc  = fmaxf(cnt, 1.0f);
        bool  ok  = cnt > 1.0f;
        float mean = ok ? (S1 / cc) : S1;
        float var  = (S2 - 2.0f * mean * S1 + (float)S * mean * mean) / cc;
        float inv  = ok ? rsqrtf(var + 1e-6f) : 1.0f;
        float a = inv * wv;
        float c = bv - mean * a;
        smem[OFF_A + tid] = a;
        smem[OFF_C + tid] = c;
    }
    __syncthreads();

    // ---- Phase D: epilogue from self-owned smem; out = x*(al*a) + c ---
    const int d0 = tx * 4;
    const float a0 = smem[OFF_A + d0 + 0], a1 = smem[OFF_A + d0 + 1];
    const float a2 = smem[OFF_A + d0 + 2], a3 = smem[OFF_A + d0 + 3];
    const float c0 = smem[OFF_C + d0 + 0], c1 = smem[OFF_C + d0 + 1];
    const float c2 = smem[OFF_C + d0 + 2], c3 = smem[OFF_C + d0 + 3];

    #pragma unroll
    for (int i = 0; i < 7; i++) {
        int s = ty + 32 * i;
        if (s < S) {
            float al = (float)((amask >> i) & 1u);
            float4 v = datav[s * 8 + tx];
            float4 o;
            o.x = fmaf(v.x, al * a0, c0);
            o.y = fmaf(v.y, al * a1, c1);
            o.z = fmaf(v.z, al * a2, c2);
            o.w = fmaf(v.w, al * a3, c3);
            __stcs(reinterpret_cast<float4*>(outp + (size_t)s * D_FEAT) + tx, o);
        }
    }
}

extern "C" void kernel_launch(void* const* d_in, const int* in_sizes, int n_in,
                              void* d_out, int out_size)
{
    const float* x      = (const float*)d_in[0];
    const int*   mask   = (const int*)d_in[1];
    const float* w_obj  = (const float*)d_in[2];
    const float* b_obj  = (const float*)d_in[3];
    const float* w_road = (const float*)d_in[4];
    const float* b_road = (const float*)d_in[5];
    float* out = (float*)d_out;

    cudaFuncSetAttribute(cross_set_norm_kernel,
                         cudaFuncAttributeMaxDynamicSharedMemorySize, SMEM_BYTES);

    dim3 grid(B_TOT * 16);   // b * (2 segs) * (8 feature eighths)
    dim3 block(NTHREADS);
    cross_set_norm_kernel<<<grid, block, SMEM_BYTES>>>(
        x, mask, w_obj, b_obj, w_road, b_road, out);
}

// round 10
// speedup vs baseline: 1.0061x; 1.0061x over previous
#include <cuda_runtime.h>
#include <cuda_bf16.h>
#include <cstdint>

// CrossSetNorm: x[B=2048, S=328, D=256] f32, mask[B,S] int32 (nonzero = dead).
// R10: R8 structure (eighth tiles, 25KB, 256 thr, 8 CTAs/SM, barrier-free
// cp.async load->sum on self-owned data) with overhead cuts:
//  - popc-based alive count (atomicAdd), no smem mask copy / count warp
//  - single-stage partial fold (2 post-sum barriers instead of 4)

#define B_TOT   2048
#define S_TOT   328
#define D_FEAT  256
#define D_8TH   32
#define S_OBJ   128
#define S_ROAD  200
#define NTHREADS 256

// Shared memory layout (float slots), per CTA:
//   [0, 6400)       raw x tile (200 rows x 8 float4)
//   [6400, 6656)    r1 partials [8][32]
//   [6656, 6912)    r2 partials [8][32]
//   [6912, 6944)    a[32]
//   [6944, 6976)    c[32]
//   [6976]          count (int)
#define OFF_DATA   0
#define OFF_R1     6400
#define OFF_R2     6656
#define OFF_A      6912
#define OFF_C      6944
#define OFF_CNT    6976
#define SMEM_FLOATS 6980
#define SMEM_BYTES (SMEM_FLOATS * 4)   // 27920 B; x8 CTAs ~= 223KB/SM

__device__ __forceinline__ void cp_async16(uint32_t smem_addr, const void* gptr) {
    asm volatile("cp.async.cg.shared.global [%0], [%1], 16;\n"
                 :: "r"(smem_addr), "l"(gptr) : "memory");
}

__global__ void __launch_bounds__(NTHREADS, 8)
cross_set_norm_kernel(const float* __restrict__ x,
                      const int* __restrict__ mask,
                      const float* __restrict__ w_obj,
                      const float* __restrict__ b_obj,
                      const float* __restrict__ w_road,
                      const float* __restrict__ b_road,
                      float* __restrict__ out)
{
    extern __shared__ float smem[];
    int* scnt = reinterpret_cast<int*>(smem + OFF_CNT);

    const int bid    = blockIdx.x;
    const int eighth = bid & 7;           // feature eighth
    const int seg    = (bid >> 3) & 1;    // 0 = obj, 1 = road
    const int b      = bid >> 4;

    const int S   = seg ? S_ROAD : S_OBJ;
    const int off = seg ? S_OBJ : 0;
    const int fo  = eighth * D_8TH;
    const float* __restrict__ wseg = (seg ? w_road : w_obj) + fo;
    const float* __restrict__ bseg = (seg ? b_road : b_obj) + fo;

    const size_t row_base = ((size_t)b * S_TOT + off);
    const float* xin  = x    + row_base * D_FEAT + fo;
    float*       outp = out  + row_base * D_FEAT + fo;
    const int*   m    = mask + row_base;

    const int tid  = threadIdx.x;
    const int tx   = tid & 7;    // float4 column: features [4*tx, 4*tx+4) in eighth
    const int ty   = tid >> 3;   // 0..31 row
    const int lane = tid & 31;
    const int wrp  = tid >> 5;   // 0..7
    const unsigned FULL = 0xffffffffu;

    // ---- Phase A: fire tile via cp.async in two commit groups ---------
    uint32_t sdata = (uint32_t)__cvta_generic_to_shared(smem + OFF_DATA);
    const float* gsrc = xin + (size_t)ty * D_FEAT + tx * 4;
    uint32_t sdst = sdata + (uint32_t)(ty * 8 + tx) * 16;
    // group A: rows ty, ty+32, ty+64 (always < 96 <= S)
    #pragma unroll
    for (int i = 0; i < 3; i++) {
        cp_async16(sdst, gsrc);
        sdst += 32 * 8 * 16;
        gsrc += 32 * D_FEAT;
    }
    asm volatile("cp.async.commit_group;\n" ::: "memory");
    // group B: remaining rows
    #pragma unroll
    for (int i = 3; i < 7; i++) {
        if (ty + 32 * i < S) {
            cp_async16(sdst, gsrc);
        }
        sdst += 32 * 8 * 16;
        gsrc += 32 * D_FEAT;
    }
    asm volatile("cp.async.commit_group;\n" ::: "memory");

    // per-thread alive bitmask for own rows (independent LDGs, L1/L2-hot)
    unsigned amask = 0;
    #pragma unroll
    for (int i = 0; i < 7; i++) {
        int s = ty + 32 * i;
        if (s < S && __ldg(m + s) == 0) amask |= (1u << i);
    }
    // prefetch per-feature weight/bias for the coeff phase
    float wv = 0.f, bv = 0.f;
    if (tid < D_8TH) { wv = __ldg(wseg + tid); bv = __ldg(bseg + tid); }

    // count: zero, barrier, popc-atomic from the 32 tx==0 threads
    if (tid == 0) *scnt = 0;
    __syncthreads();
    if (tx == 0) atomicAdd(scnt, (int)__popc(amask));

    float4* datav = reinterpret_cast<float4*>(smem + OFF_DATA);

    // ---- Phase B: barrier-free sum of self-owned data -----------------
    float s1x = 0.f, s1y = 0.f, s1z = 0.f, s1w = 0.f;
    float s2x = 0.f, s2y = 0.f, s2z = 0.f, s2w = 0.f;

    asm volatile("cp.async.wait_group 1;\n" ::: "memory");
    #pragma unroll
    for (int i = 0; i < 3; i++) {
        int s = ty + 32 * i;
        float al = (float)((amask >> i) & 1u);
        float4 v = datav[s * 8 + tx];
        v.x *= al; v.y *= al; v.z *= al; v.w *= al;
        s1x += v.x; s1y += v.y; s1z += v.z; s1w += v.w;
        s2x += v.x * v.x; s2y += v.y * v.y; s2z += v.z * v.z; s2w += v.w * v.w;
    }
    asm volatile("cp.async.wait_group 0;\n" ::: "memory");
    #pragma unroll
    for (int i = 3; i < 7; i++) {
        int s = ty + 32 * i;
        if (s < S) {
            float al = (float)((amask >> i) & 1u);
            float4 v = datav[s * 8 + tx];
            v.x *= al; v.y *= al; v.z *= al; v.w *= al;
            s1x += v.x; s1y += v.y; s1z += v.z; s1w += v.w;
            s2x += v.x * v.x; s2y += v.y * v.y; s2z += v.z * v.z; s2w += v.w * v.w;
        }
    }

    // intra-warp folds (lane layout: tx=lane&7, rowgrp=lane>>3)
    s1x += __shfl_down_sync(FULL, s1x, 16); s1y += __shfl_down_sync(FULL, s1y, 16);
    s1z += __shfl_down_sync(FULL, s1z, 16); s1w += __shfl_down_sync(FULL, s1w, 16);
    s2x += __shfl_down_sync(FULL, s2x, 16); s2y += __shfl_down_sync(FULL, s2y, 16);
    s2z += __shfl_down_sync(FULL, s2z, 16); s2w += __shfl_down_sync(FULL, s2w, 16);
    s1x += __shfl_down_sync(FULL, s1x, 8);  s1y += __shfl_down_sync(FULL, s1y, 8);
    s1z += __shfl_down_sync(FULL, s1z, 8);  s1w += __shfl_down_sync(FULL, s1w, 8);
    s2x += __shfl_down_sync(FULL, s2x, 8);  s2y += __shfl_down_sync(FULL, s2y, 8);
    s2z += __shfl_down_sync(FULL, s2z, 8);  s2w += __shfl_down_sync(FULL, s2w, 8);

    // single-stage fold: every warp writes its lane<8 partials
    float4* r1 = reinterpret_cast<float4*>(smem + OFF_R1);
    float4* r2 = reinterpret_cast<float4*>(smem + OFF_R2);
    if (lane < 8) {
        r1[wrp * 8 + lane] = make_float4(s1x, s1y, s1z, s1w);
        r2[wrp * 8 + lane] = make_float4(s2x, s2y, s2z, s2w);
    }
    __syncthreads();

    // ---- Phase C: final reduce + coefficients (32 threads) ------------
    if (tid < D_8TH) {
        float S1 = 0.f, S2 = 0.f;
        #pragma unroll
        for (int k = 0; k < 8; k++) {
            S1 += smem[OFF_R1 + k * 32 + tid];
            S2 += smem[OFF_R2 + k * 32 + tid];
        }
        int   cnti = *scnt;
        float cnt  = (float)cnti;
        float cc   = fmaxf(cnt, 1.0f);
        bool  ok   = cnti > 1;
        float mean = ok ? (S1 / cc) : S1;
        float var  = (S2 - 2.0f * mean * S1 + (float)S * mean * mean) / cc;
        float inv  = ok ? rsqrtf(var + 1e-6f) : 1.0f;
        float a = inv * wv;
        float c = bv - mean * a;
        smem[OFF_A + tid] = a;
        smem[OFF_C + tid] = c;
    }
    __syncthreads();

    // ---- Phase D: epilogue from self-owned smem; out = x*(al*a) + c ---
    const int d0 = tx * 4;
    const float a0 = smem[OFF_A + d0 + 0], a1 = smem[OFF_A + d0 + 1];
    const float a2 = smem[OFF_A + d0 + 2], a3 = smem[OFF_A + d0 + 3];
    const float c0 = smem[OFF_C + d0 + 0], c1 = smem[OFF_C + d0 + 1];
    const float c2 = smem[OFF_C + d0 + 2], c3 = smem[OFF_C + d0 + 3];

    float4* odst = reinterpret_cast<float4*>(outp + (size_t)ty * D_FEAT) + tx;
    #pragma unroll
    for (int i = 0; i < 7; i++) {
        int s = ty + 32 * i;
        if (s < S) {
            float al = (float)((amask >> i) & 1u);
            float4 v = datav[s * 8 + tx];
            float4 o;
            o.x = fmaf(v.x, al * a0, c0);
            o.y = fmaf(v.y, al * a1, c1);
            o.z = fmaf(v.z, al * a2, c2);
            o.w = fmaf(v.w, al * a3, c3);
            __stcs(odst, o);
        }
        odst += 32 * (D_FEAT / 4);
    }
}

extern "C" void kernel_launch(void* const* d_in, const int* in_sizes, int n_in,
                              void* d_out, int out_size)
{
    const float* x      = (const float*)d_in[0];
    const int*   mask   = (const int*)d_in[1];
    const float* w_obj  = (const float*)d_in[2];
    const float* b_obj  = (const float*)d_in[3];
    const float* w_road = (const float*)d_in[4];
    const float* b_road = (const float*)d_in[5];
    float* out = (float*)d_out;

    cudaFuncSetAttribute(cross_set_norm_kernel,
                         cudaFuncAttributeMaxDynamicSharedMemorySize, SMEM_BYTES);

    dim3 grid(B_TOT * 16);   // b * (2 segs) * (8 feature eighths)
    dim3 block(NTHREADS);
    cross_set_norm_kernel<<<grid, block, SMEM_BYTES>>>(
        x, mask, w_obj, b_obj, w_road, b_road, out);
}